// round 16
// baseline (speedup 1.0000x reference)
#include <cuda_runtime.h>
#include <cuda_fp16.h>
#include <cstdint>

#define PPIX 3136
#define CH 256
#define DIM 32
#define KER 7
#define K2 49
#define TILE 14
#define HALO 20
#define HALOSZ 400
#define HROW 40     // halfs per halo row (32 ch + pad), 80B, 16B-aligned
#define SROW 50     // floats per score row (49 + pad)

// scratch (allocation-free rule: device globals)
__device__ __align__(16) __half g_Xq[2 * PPIX * CH];   // queries, (P,C) fp16
__device__ __align__(16) __half g_Xk[2 * PPIX * CH];   // key,     (P,C) fp16
__device__ __align__(16) __half g_Qh[2 * PPIX * CH];
__device__ __align__(16) __half g_Kh[2 * PPIX * CH];
__device__ __align__(16) __half g_Vh[2 * PPIX * CH];
__device__ __align__(16) __half g_Oh[2 * PPIX * CH];   // attention output
__device__ __align__(16) __half g_Whi[3 * CH * CH];    // fp16 Wq,Wk,Wv
__device__ __align__(16) __half g_Who[CH * CH];        // fp16 Wout
__device__ __align__(16) float  g_bias2[CH];           // Wout*bcv + bout

// ---------------------------------------------------------------------------
// helpers
// ---------------------------------------------------------------------------
__device__ __forceinline__ uint32_t h2_as_u32(__half2 h) {
    return *reinterpret_cast<uint32_t*>(&h);
}
__device__ __forceinline__ void mma_f16(float c[4], const uint32_t a[4], const uint32_t b[2]) {
    asm volatile(
        "mma.sync.aligned.m16n8k16.row.col.f32.f16.f16.f32 "
        "{%0,%1,%2,%3}, {%4,%5,%6,%7}, {%8,%9}, {%0,%1,%2,%3};"
        : "+f"(c[0]), "+f"(c[1]), "+f"(c[2]), "+f"(c[3])
        : "r"(a[0]), "r"(a[1]), "r"(a[2]), "r"(a[3]), "r"(b[0]), "r"(b[1]));
}
__device__ __forceinline__ void cp16(void* smem_dst, const void* gmem_src) {
    uint32_t s = (uint32_t)__cvta_generic_to_shared(smem_dst);
    asm volatile("cp.async.cg.shared.global [%0], [%1], 16;" :: "r"(s), "l"(gmem_src));
}
#define CP_COMMIT()  asm volatile("cp.async.commit_group;")
#define CP_WAIT1()   asm volatile("cp.async.wait_group 1;")
#define CP_WAIT0()   asm volatile("cp.async.wait_group 0;")

#define OHROW 72                     // halves per GEMM smem row (64 + 8 pad)
#define GEMM_STGH (2 * 64 * OHROW)   // halves per stage: A[64][72] + B[64][72]

// ---------------------------------------------------------------------------
// prep: fused input transpose+convert AND weight convert.
// Blocks [0, 3136): (n,C,P) fp32 -> (n,P,C) fp16 via 32x32 smem tiles.
// Blocks [3136, 3392): weights fp32 -> fp16 (in_proj then out_proj).
// 256 threads per block.
// ---------------------------------------------------------------------------
__global__ void prep_kernel(const float* __restrict__ q, const float* __restrict__ k,
                            const float* __restrict__ ipw, const float* __restrict__ opw) {
    int b = blockIdx.x;
    if (b < 3136) {
        __shared__ float t[32][33];
        int bx = b % 98;            // pixel tile (98 * 32 = 3136)
        int by = (b / 98) & 7;      // channel tile (8 * 32 = 256)
        int z  = b / 784;           // src*2 + n
        int src = z >> 1, n = z & 1;
        const float* In = (src ? k : q) + (size_t)n * CH * PPIX;
        __half* Out = (src ? g_Xk : g_Xq) + (size_t)n * PPIX * CH;
        int p0 = bx * 32, c0 = by * 32;
        int tx = threadIdx.x & 31, ty = threadIdx.x >> 5;   // ty 0..7
        #pragma unroll
        for (int i = 0; i < 4; i++) {
            int c = ty + i * 8;
            t[c][tx] = In[(size_t)(c0 + c) * PPIX + p0 + tx];
        }
        __syncthreads();
        #pragma unroll
        for (int i = 0; i < 4; i++) {
            int p = ty + i * 8;
            Out[(size_t)(p0 + p) * CH + c0 + tx] = __float2half_rn(t[tx][p]);
        }
    } else {
        int i = (b - 3136) * 256 + threadIdx.x;             // float4 index, 65536 total
        const int IPW4 = 3 * CH * CH / 4;                    // 49152
        float4 v = (i < IPW4) ? reinterpret_cast<const float4*>(ipw)[i]
                              : reinterpret_cast<const float4*>(opw)[i - IPW4];
        __half2 h0 = __floats2half2_rn(v.x, v.y);
        __half2 h1 = __floats2half2_rn(v.z, v.w);
        uint2 packed = make_uint2(h2_as_u32(h0), h2_as_u32(h1));
        if (i < IPW4) *reinterpret_cast<uint2*>(g_Whi + i * 4) = packed;
        else          *reinterpret_cast<uint2*>(g_Who + (i - IPW4) * 4) = packed;
    }
}

// ---------------------------------------------------------------------------
// bias_fused (single block, 1024 threads, 4 threads per channel):
//   phase 1: bcv[c] = pos * sum_j Wv[c][j] + bv[c]         -> smem
//   phase 2: bias2[c] = sum_k Wout[c][k] * bcv[k] + bout[c] -> g_bias2
// K-side pos bias cancels exactly in softmax and is never materialized.
// ---------------------------------------------------------------------------
__global__ void __launch_bounds__(1024, 1)
bias_fused(const float* __restrict__ ipw, const float* __restrict__ ipb,
           const float* __restrict__ opw, const float* __restrict__ opb,
           const float* __restrict__ pos) {
    __shared__ float sbcv[CH];
    int tid = threadIdx.x;
    int c = tid >> 2;          // 0..255
    int sub = tid & 3;         // 4 threads per channel

    // phase 1: rowsum of Wv row c
    {
        const float4* wv = reinterpret_cast<const float4*>(ipw + (size_t)(2 * CH + c) * CH);
        float s = 0.f;
        #pragma unroll
        for (int i = 0; i < 16; i++) {
            float4 v = wv[sub + i * 4];
            s += v.x + v.y + v.z + v.w;
        }
        s += __shfl_xor_sync(0xffffffffu, s, 1);
        s += __shfl_xor_sync(0xffffffffu, s, 2);
        if (sub == 0) sbcv[c] = pos[0] * s + ipb[2 * CH + c];
    }
    __syncthreads();

    // phase 2: bias2[c] = Wout[c] . bcv + bout[c]
    {
        const float4* wo = reinterpret_cast<const float4*>(opw + (size_t)c * CH);
        const float4* bv = reinterpret_cast<const float4*>(sbcv);
        float s = 0.f;
        #pragma unroll
        for (int i = 0; i < 16; i++) {
            float4 w = wo[sub + i * 4];
            float4 x = bv[sub + i * 4];
            s += w.x * x.x + w.y * x.y + w.z * x.z + w.w * x.w;
        }
        s += __shfl_xor_sync(0xffffffffu, s, 1);
        s += __shfl_xor_sync(0xffffffffu, s, 2);
        if (sub == 0) g_bias2[c] = s + opb[c];
    }
}

// ---------------------------------------------------------------------------
// Q/K/V projection (fp16 HMMA m16n8k16, BM=64 BN=64 BK=64, cp.async 2-stage,
// 128 threads / 4 warps 2m x 2n):  Out[p][c'] = sum_c X[p][c] * W[c'][c]
// grid (49, 4, 6): z = pr*2 + n.  Q adds bias (fp32), all outputs fp16.
// ---------------------------------------------------------------------------
__global__ void __launch_bounds__(128, 5)
proj_gemm(const float* __restrict__ ipb) {
    extern __shared__ __half smh[];     // [2][GEMM_STGH]
    int pr = blockIdx.z >> 1;
    int n  = blockIdx.z & 1;
    const __half* A = (pr == 0 ? g_Xq : g_Xk) + (size_t)n * PPIX * CH;
    const __half* B = g_Whi + (size_t)pr * CH * CH;
    __half* Out = (pr == 0 ? g_Qh : (pr == 1 ? g_Kh : g_Vh)) + (size_t)n * PPIX * CH;

    int tid = threadIdx.x;
    int m0 = blockIdx.x * 64;
    int c0 = blockIdx.y * 64;
    int w = tid >> 5, lane = tid & 31;
    int r = lane >> 2, tig = lane & 3;
    int wm = (w & 1) * 32;
    int wn = (w >> 1) * 32;

    float acc[2][4][4] = {};

    auto issue_tile = [&](int t) {
        __half* base = smh + (t & 1) * GEMM_STGH;
        int kt = t * 64;
        #pragma unroll
        for (int i = 0; i < 4; i++) {
            int id = tid + 128 * i;
            int row = id >> 3;                 // 0..63
            int k8 = (id & 7) * 8;             // 0..56
            cp16(base + row * OHROW + k8,
                 A + (size_t)(m0 + row) * CH + kt + k8);
            cp16(base + 64 * OHROW + row * OHROW + k8,
                 B + (size_t)(c0 + row) * CH + kt + k8);
        }
        CP_COMMIT();
    };

    issue_tile(0);

    for (int it = 0; it < 4; it++) {
        if (it + 1 < 4) { issue_tile(it + 1); CP_WAIT1(); }
        else            { CP_WAIT0(); }
        __syncthreads();

        const __half* base = smh + (it & 1) * GEMM_STGH;
        const __half* Bb = base + 64 * OHROW;
        #pragma unroll
        for (int ks = 0; ks < 4; ks++) {
            int k0 = ks * 16;
            uint32_t a[2][4], b[4][2];
            #pragma unroll
            for (int mt = 0; mt < 2; mt++) {
                int m = wm + mt * 16 + r;
                a[mt][0] = *reinterpret_cast<const uint32_t*>(base + m * OHROW + k0 + 2 * tig);
                a[mt][1] = *reinterpret_cast<const uint32_t*>(base + (m + 8) * OHROW + k0 + 2 * tig);
                a[mt][2] = *reinterpret_cast<const uint32_t*>(base + m * OHROW + k0 + 2 * tig + 8);
                a[mt][3] = *reinterpret_cast<const uint32_t*>(base + (m + 8) * OHROW + k0 + 2 * tig + 8);
            }
            #pragma unroll
            for (int nt = 0; nt < 4; nt++) {
                int nn = wn + nt * 8 + r;
                b[nt][0] = *reinterpret_cast<const uint32_t*>(Bb + nn * OHROW + k0 + 2 * tig);
                b[nt][1] = *reinterpret_cast<const uint32_t*>(Bb + nn * OHROW + k0 + 2 * tig + 8);
            }
            #pragma unroll
            for (int mt = 0; mt < 2; mt++)
                #pragma unroll
                for (int nt = 0; nt < 4; nt++)
                    mma_f16(acc[mt][nt], a[mt], b[nt]);
        }
        __syncthreads();
    }

    // epilogue: bias for Q (fp32 add), store fp16 half2 pairs
    #pragma unroll
    for (int mt = 0; mt < 2; mt++) {
        int row0 = m0 + wm + mt * 16 + r;
        #pragma unroll
        for (int nt = 0; nt < 4; nt++) {
            int cc = c0 + wn + nt * 8 + 2 * tig;
            float b0 = (pr == 0) ? ipb[cc] : 0.f;
            float b1 = (pr == 0) ? ipb[cc + 1] : 0.f;
            __half2 v0 = __floats2half2_rn(acc[mt][nt][0] + b0, acc[mt][nt][1] + b1);
            __half2 v1 = __floats2half2_rn(acc[mt][nt][2] + b0, acc[mt][nt][3] + b1);
            *reinterpret_cast<uint32_t*>(Out + (size_t)row0 * CH + cc)       = h2_as_u32(v0);
            *reinterpret_cast<uint32_t*>(Out + (size_t)(row0 + 8) * CH + cc) = h2_as_u32(v1);
        }
    }
}

// ---------------------------------------------------------------------------
// Local attention: thread PAIR per pixel (16 channels each), 512 threads,
// fp16 K/V halos (straight 16B copies) + f32 score rows in smem, 2 CTAs/SM.
// Output = pure attention average (bcv folded into bias2), fp16.
// ---------------------------------------------------------------------------
__global__ void __launch_bounds__(512, 2) attn_kernel() {
    extern __shared__ char smraw[];
    __half* Ks = reinterpret_cast<__half*>(smraw);
    __half* Vs = Ks + HALOSZ * HROW;
    float*  Ssc = reinterpret_cast<float*>(smraw + 2 * HALOSZ * HROW * sizeof(__half));

    int tx0 = blockIdx.x * TILE;
    int ty0 = blockIdx.y * TILE;
    int h = blockIdx.z & 7;
    int n = blockIdx.z >> 3;
    int tid = threadIdx.x;
    int cbase = h * DIM;

    const __half* Kp = g_Kh + (size_t)n * PPIX * CH;
    const __half* Vp = g_Vh + (size_t)n * PPIX * CH;

    for (int idx = tid; idx < HALOSZ * 4 * 2; idx += 512) {
        int m = idx >= HALOSZ * 4;
        int j = m ? idx - HALOSZ * 4 : idx;
        int hp = j >> 2;
        int c8 = (j & 3) * 8;
        int gy = ty0 - 3 + hp / HALO;
        int gx = tx0 - 3 + hp % HALO;
        uint4 v = make_uint4(0u, 0u, 0u, 0u);
        if (gy >= 0 && gy < 56 && gx >= 0 && gx < 56)
            v = *reinterpret_cast<const uint4*>(
                (m ? Vp : Kp) + (size_t)(gy * 56 + gx) * CH + cbase + c8);
        *reinterpret_cast<uint4*>((m ? Vs : Ks) + hp * HROW + c8) = v;
    }
    __syncthreads();

    if (tid >= 2 * TILE * TILE) return;
    int pix = tid >> 1;
    int half = tid & 1;
    unsigned msk = (tid < 384) ? 0xffffffffu : 0xffu;
    int ly = pix / TILE, lx = pix % TILE;
    int p = (ty0 + ly) * 56 + (tx0 + lx);
    int coff = half * 16;
    float* srow = Ssc + pix * SROW;

    const float scale = 0.17677669529663687f;
    float2 q2[8];
    {
        const __half* qptr = g_Qh + (size_t)n * PPIX * CH + (size_t)p * CH + cbase + coff;
        __half2 qh[8];
        *reinterpret_cast<uint4*>(qh)     = *reinterpret_cast<const uint4*>(qptr);
        *reinterpret_cast<uint4*>(qh + 4) = *reinterpret_cast<const uint4*>(qptr + 8);
        #pragma unroll
        for (int i = 0; i < 8; i++) {
            float2 f = __half22float2(qh[i]);
            q2[i] = make_float2(f.x * scale, f.y * scale);
        }
    }

    float mx = -1e30f;
    #pragma unroll
    for (int ti = 0; ti < KER; ti++) {
        #pragma unroll
        for (int tj = 0; tj < KER; tj++) {
            const __half* kr = Ks + ((ly + ti) * HALO + (lx + tj)) * HROW + coff;
            __half2 hh[8];
            *reinterpret_cast<uint4*>(hh)     = *reinterpret_cast<const uint4*>(kr);
            *reinterpret_cast<uint4*>(hh + 4) = *reinterpret_cast<const uint4*>(kr + 8);
            float s0 = 0.f, s1 = 0.f;
            #pragma unroll
            for (int i = 0; i < 8; i++) {
                float2 f = __half22float2(hh[i]);
                s0 += q2[i].x * f.x;
                s1 += q2[i].y * f.y;
            }
            float s = s0 + s1;
            s += __shfl_xor_sync(msk, s, 1);
            if (half == 0) srow[ti * KER + tj] = s;
            mx = fmaxf(mx, s);
        }
    }
    __syncwarp(msk);

    float sum = 0.f;
    #pragma unroll
    for (int t = 0; t < K2; t++) {
        float wgt = __expf(srow[t] - mx);
        sum += wgt;
        if (half == 0) srow[t] = wgt;
    }
    __syncwarp(msk);
    float inv = 1.f / sum;

    float2 o2[8];
    #pragma unroll
    for (int i = 0; i < 8; i++) o2[i] = make_float2(0.f, 0.f);
    #pragma unroll
    for (int ti = 0; ti < KER; ti++) {
        #pragma unroll
        for (int tj = 0; tj < KER; tj++) {
            const __half* vr = Vs + ((ly + ti) * HALO + (lx + tj)) * HROW + coff;
            __half2 hh[8];
            *reinterpret_cast<uint4*>(hh)     = *reinterpret_cast<const uint4*>(vr);
            *reinterpret_cast<uint4*>(hh + 4) = *reinterpret_cast<const uint4*>(vr + 8);
            float wgt = srow[ti * KER + tj];
            #pragma unroll
            for (int i = 0; i < 8; i++) {
                float2 f = __half22float2(hh[i]);
                o2[i].x += wgt * f.x;
                o2[i].y += wgt * f.y;
            }
        }
    }

    __half* optr = g_Oh + (size_t)n * PPIX * CH + (size_t)p * CH + cbase + coff;
    __half2 oh[8];
    #pragma unroll
    for (int i = 0; i < 8; i++)
        oh[i] = __floats2half2_rn(o2[i].x * inv, o2[i].y * inv);
    *reinterpret_cast<uint4*>(optr)     = *reinterpret_cast<uint4*>(oh);
    *reinterpret_cast<uint4*>(optr + 8) = *reinterpret_cast<uint4*>(oh + 4);
}

// ---------------------------------------------------------------------------
// Out projection, per-batch (fp16 HMMA m16n8k16, BM=64 BN=64 BK=64, cp.async
// 2-stage, 128 threads / 4 warps 2m x 2n, grid (49,4,2)):
//   out[n][c'][p] = sum_c Oh[n][p][c] * Who[c'][c] + bias2[c']
// ---------------------------------------------------------------------------
__global__ void __launch_bounds__(128, 5)
outproj_gemm(float* __restrict__ out) {
    extern __shared__ __half smh[];     // [2][GEMM_STGH]
    int nb = blockIdx.z;
    const __half* Oh = g_Oh + (size_t)nb * PPIX * CH;

    int tid = threadIdx.x;
    int m0 = blockIdx.x * 64;
    int c0 = blockIdx.y * 64;
    int w = tid >> 5, lane = tid & 31;
    int r = lane >> 2, tig = lane & 3;
    int wm = (w & 1) * 32;
    int wn = (w >> 1) * 32;

    float acc[2][4][4] = {};

    auto issue_tile = [&](int t) {
        __half* base = smh + (t & 1) * GEMM_STGH;
        int kt = t * 64;
        #pragma unroll
        for (int i = 0; i < 4; i++) {
            int id = tid + 128 * i;
            int row = id >> 3;
            int k8 = (id & 7) * 8;
            cp16(base + row * OHROW + k8,
                 Oh + (size_t)(m0 + row) * CH + kt + k8);
            cp16(base + 64 * OHROW + row * OHROW + k8,
                 g_Who + (size_t)(c0 + row) * CH + kt + k8);
        }
        CP_COMMIT();
    };

    issue_tile(0);

    for (int it = 0; it < 4; it++) {
        if (it + 1 < 4) { issue_tile(it + 1); CP_WAIT1(); }
        else            { CP_WAIT0(); }
        __syncthreads();

        const __half* base = smh + (it & 1) * GEMM_STGH;
        const __half* Bb = base + 64 * OHROW;
        #pragma unroll
        for (int ks = 0; ks < 4; ks++) {
            int k0 = ks * 16;
            uint32_t a[2][4], b[4][2];
            #pragma unroll
            for (int mt = 0; mt < 2; mt++) {
                int m = wm + mt * 16 + r;
                a[mt][0] = *reinterpret_cast<const uint32_t*>(base + m * OHROW + k0 + 2 * tig);
                a[mt][1] = *reinterpret_cast<const uint32_t*>(base + (m + 8) * OHROW + k0 + 2 * tig);
                a[mt][2] = *reinterpret_cast<const uint32_t*>(base + m * OHROW + k0 + 2 * tig + 8);
                a[mt][3] = *reinterpret_cast<const uint32_t*>(base + (m + 8) * OHROW + k0 + 2 * tig + 8);
            }
            #pragma unroll
            for (int nt = 0; nt < 4; nt++) {
                int nn = wn + nt * 8 + r;
                b[nt][0] = *reinterpret_cast<const uint32_t*>(Bb + nn * OHROW + k0 + 2 * tig);
                b[nt][1] = *reinterpret_cast<const uint32_t*>(Bb + nn * OHROW + k0 + 2 * tig + 8);
            }
            #pragma unroll
            for (int mt = 0; mt < 2; mt++)
                #pragma unroll
                for (int nt = 0; nt < 4; nt++)
                    mma_f16(acc[mt][nt], a[mt], b[nt]);
        }
        __syncthreads();
    }

    float* ob = out + (size_t)nb * CH * PPIX;
    #pragma unroll
    for (int mt = 0; mt < 2; mt++) {
        int row0 = m0 + wm + mt * 16 + r;
        #pragma unroll
        for (int nt = 0; nt < 4; nt++) {
            int cc = c0 + wn + nt * 8 + 2 * tig;
            float b0 = g_bias2[cc], b1 = g_bias2[cc + 1];
            ob[(size_t)cc * PPIX + row0]           = acc[mt][nt][0] + b0;
            ob[(size_t)(cc + 1) * PPIX + row0]     = acc[mt][nt][1] + b1;
            ob[(size_t)cc * PPIX + row0 + 8]       = acc[mt][nt][2] + b0;
            ob[(size_t)(cc + 1) * PPIX + row0 + 8] = acc[mt][nt][3] + b1;
        }
    }
}

extern "C" void kernel_launch(void* const* d_in, const int* in_sizes, int n_in,
                              void* d_out, int out_size) {
    const float* queries = (const float*)d_in[0];
    const float* key     = (const float*)d_in[1];
    const float* pos     = (const float*)d_in[2];
    const float* ipw     = (const float*)d_in[3];
    const float* ipb     = (const float*)d_in[4];
    const float* opw     = (const float*)d_in[5];
    const float* opb     = (const float*)d_in[6];
    float* out = (float*)d_out;

    const int gemm_smem = 2 * GEMM_STGH * (int)sizeof(__half);      // 36864
    const int attn_smem = 2 * HALOSZ * HROW * (int)sizeof(__half)
                        + TILE * TILE * SROW * (int)sizeof(float);  // 103200

    cudaFuncSetAttribute(proj_gemm,    cudaFuncAttributeMaxDynamicSharedMemorySize, gemm_smem);
    cudaFuncSetAttribute(outproj_gemm, cudaFuncAttributeMaxDynamicSharedMemorySize, gemm_smem);
    cudaFuncSetAttribute(attn_kernel,  cudaFuncAttributeMaxDynamicSharedMemorySize, attn_smem);

    prep_kernel<<<3392, 256>>>(queries, key, ipw, opw);
    bias_fused<<<1, 1024>>>(ipw, ipb, opw, opb, pos);
    proj_gemm<<<dim3(49, 4, 6), 128, gemm_smem>>>(ipb);
    attn_kernel<<<dim3(4, 4, 16), 512, attn_smem>>>();
    outproj_gemm<<<dim3(49, 4, 2), 128, gemm_smem>>>(out);
}